// round 2
// baseline (speedup 1.0000x reference)
#include <cuda_runtime.h>
#include <math.h>

// ---------------------------------------------------------------------------
// DeepSeek V3 MLA layer, fp32 baseline.
// B=2, T=1024, HID=4096, H=32, D_NOPE=128, D_ROPE=64, D_V=128, D_QK=192,
// Q_RANK=1536, KV_RANK=512.
// Pipeline:
//   1. qlow = x @ wq_a                      [2048,1536]
//   2. rmsnorm(qlow) (in place)
//   3. q    = qlow @ wq_b                   [2048,6144]  (H*D_QK)
//   4. kvout= x @ wkv_a                     [2048,576]   (KV_RANK + D_ROPE)
//   5. rmsnorm(kvout[:, :512]) in place
//   6. rope(q pe cols), rope(kvout[:,512:576])
//   7. kvexp= kvout[:, :512] @ wkv_b        [2048,8192]  (H*(D_NOPE+D_V))
//   8. scores[b,h] = scale * Qh @ [k_nope | k_pe]^T  + causal/pad mask
//   9. row softmax over scores
//  10. attn_out[b,h] = scores[b,h] @ V_h    (causal-trimmed K loop)
//  11. out  = attn_out @ wo                 [2048,4096]
// ---------------------------------------------------------------------------

#define NTOK 2048            // B*T
#define TT   1024
#define NH   32

// device scratch (no cudaMalloc allowed)
__device__ float g_qlow [2048 * 1536];
__device__ float g_q    [2048 * 6144];
__device__ float g_kvout[2048 * 576];
__device__ float g_kvexp[2048 * 8192];
__device__ float g_scores[64ll * 1024 * 1024];   // [B*H][T][T] 268MB
__device__ float g_attn [2048 * 4096];

// ---------------------------------------------------------------------------
// Generic NN SGEMM: C[M,N] = A[M,K] @ B[K,N]. 128x128x16 tiles, 8x8 micro.
// Batched via blockIdx.z with (outer, inner) stride decomposition.
// causal != 0: limit K to (m0 + 128)  (valid keys for causal attention rows).
// M must be a multiple of 128; N,K arbitrary (N guarded; K multiple of 16).
// ---------------------------------------------------------------------------
__global__ void __launch_bounds__(256, 2) gemm_nn_k(
    const float* __restrict__ Ab, const float* __restrict__ Bb,
    float* __restrict__ Cb,
    int M, int N, int K, int lda, int ldb, int ldc,
    long aOut, long aIn, long bOut, long bIn, long cOut, long cIn,
    int innerCount, int causal)
{
    int z = blockIdx.z;
    int outer = z / innerCount, inner = z - outer * innerCount;
    const float* A = Ab + (long)outer * aOut + (long)inner * aIn;
    const float* B = Bb + (long)outer * bOut + (long)inner * bIn;
    float*       C = Cb + (long)outer * cOut + (long)inner * cIn;

    __shared__ float As[16][128];
    __shared__ float Bs[16][128];

    int tid = threadIdx.x;
    int tx = tid & 15, ty = tid >> 4;
    int m0 = blockIdx.y * 128, n0 = blockIdx.x * 128;

    int Keff = causal ? min(K, m0 + 128) : K;

    float acc[8][8] = {};

    for (int k0 = 0; k0 < Keff; k0 += 16) {
        // A tile: rows m0..m0+127, k0..k0+15 -> As[k][m]
#pragma unroll
        for (int i = 0; i < 2; i++) {
            int idx = tid * 2 + i;
            int row = idx >> 2, kc = (idx & 3) << 2;
            float4 v = *(const float4*)(A + (long)(m0 + row) * lda + k0 + kc);
            As[kc + 0][row] = v.x;
            As[kc + 1][row] = v.y;
            As[kc + 2][row] = v.z;
            As[kc + 3][row] = v.w;
        }
        // B tile: rows k0..k0+15, cols n0..n0+127 -> Bs[k][n]
#pragma unroll
        for (int i = 0; i < 2; i++) {
            int idx = tid * 2 + i;
            int kr = idx >> 5, nc = (idx & 31) << 2;
            int n = n0 + nc;
            float4 v;
            if (n + 3 < N) {
                v = *(const float4*)(B + (long)(k0 + kr) * ldb + n);
            } else {
                const float* bp = B + (long)(k0 + kr) * ldb;
                v.x = (n + 0 < N) ? bp[n + 0] : 0.f;
                v.y = (n + 1 < N) ? bp[n + 1] : 0.f;
                v.z = (n + 2 < N) ? bp[n + 2] : 0.f;
                v.w = 0.f;
            }
            *(float4*)&Bs[kr][nc] = v;
        }
        __syncthreads();
#pragma unroll
        for (int k = 0; k < 16; k++) {
            float ra[8], rb[8];
            *(float4*)&ra[0] = *(const float4*)&As[k][ty * 8];
            *(float4*)&ra[4] = *(const float4*)&As[k][ty * 8 + 4];
            *(float4*)&rb[0] = *(const float4*)&Bs[k][tx * 8];
            *(float4*)&rb[4] = *(const float4*)&Bs[k][tx * 8 + 4];
#pragma unroll
            for (int i = 0; i < 8; i++)
#pragma unroll
                for (int j = 0; j < 8; j++)
                    acc[i][j] = fmaf(ra[i], rb[j], acc[i][j]);
        }
        __syncthreads();
    }

#pragma unroll
    for (int i = 0; i < 8; i++) {
        int m = m0 + ty * 8 + i;
#pragma unroll
        for (int j = 0; j < 8; j++) {
            int n = n0 + tx * 8 + j;
            if (n < N) C[(long)m * ldc + n] = acc[i][j];
        }
    }
}

// ---------------------------------------------------------------------------
// Scores: S[b,h][t][s] = scale * ( q_nope . k_nope + q_pe . k_pe ),
// masked to -1e30 above diagonal / where attention_mask==0.
// NT GEMM with gathered K operand (k_nope from kvexp, k_pe shared from kvout).
// ---------------------------------------------------------------------------
__global__ void __launch_bounds__(256, 2) scores_k(
    const float* __restrict__ q, const float* __restrict__ kvexp,
    const float* __restrict__ kvout, const int* __restrict__ amask,
    float* __restrict__ scores)
{
    int bh = blockIdx.z, b = bh >> 5, h = bh & 31;
    int m0 = blockIdx.y * 128, n0 = blockIdx.x * 128;
    float* C = scores + (long)bh * TT * TT;

    if (n0 >= m0 + 128) {          // fully above causal diagonal
        for (int e = threadIdx.x; e < 128 * 128; e += 256) {
            int i = e >> 7, j = e & 127;
            C[(long)(m0 + i) * TT + n0 + j] = -1e30f;
        }
        return;
    }

    const float* A  = q     + (long)b * TT * 6144 + h * 192;  // lda 6144
    const float* Kn = kvexp + (long)b * TT * 8192 + h * 256;  // ld 8192
    const float* Kp = kvout + (long)b * TT * 576  + 512;      // ld 576

    __shared__ float As[16][128];
    __shared__ float Bs[16][128];
    int tid = threadIdx.x, tx = tid & 15, ty = tid >> 4;

    float acc[8][8] = {};
    for (int k0 = 0; k0 < 192; k0 += 16) {
#pragma unroll
        for (int i = 0; i < 2; i++) {
            int idx = tid * 2 + i;
            int row = idx >> 2, kc = (idx & 3) << 2;
            float4 v = *(const float4*)(A + (long)(m0 + row) * 6144 + k0 + kc);
            As[kc + 0][row] = v.x;
            As[kc + 1][row] = v.y;
            As[kc + 2][row] = v.z;
            As[kc + 3][row] = v.w;
        }
#pragma unroll
        for (int i = 0; i < 2; i++) {
            int idx = tid * 2 + i;
            int row = idx >> 2, kc = (idx & 3) << 2;
            int kk = k0 + kc, s = n0 + row;
            float4 v;
            if (kk < 128) v = *(const float4*)(Kn + (long)s * 8192 + kk);
            else          v = *(const float4*)(Kp + (long)s * 576 + (kk - 128));
            Bs[kc + 0][row] = v.x;
            Bs[kc + 1][row] = v.y;
            Bs[kc + 2][row] = v.z;
            Bs[kc + 3][row] = v.w;
        }
        __syncthreads();
#pragma unroll
        for (int k = 0; k < 16; k++) {
            float ra[8], rb[8];
            *(float4*)&ra[0] = *(const float4*)&As[k][ty * 8];
            *(float4*)&ra[4] = *(const float4*)&As[k][ty * 8 + 4];
            *(float4*)&rb[0] = *(const float4*)&Bs[k][tx * 8];
            *(float4*)&rb[4] = *(const float4*)&Bs[k][tx * 8 + 4];
#pragma unroll
            for (int i = 0; i < 8; i++)
#pragma unroll
                for (int j = 0; j < 8; j++)
                    acc[i][j] = fmaf(ra[i], rb[j], acc[i][j]);
        }
        __syncthreads();
    }

    const float scale = 0.07216878364870323f;   // 192^-0.5
#pragma unroll
    for (int i = 0; i < 8; i++) {
        int t = m0 + ty * 8 + i;
#pragma unroll
        for (int j = 0; j < 8; j++) {
            int s = n0 + tx * 8 + j;
            float v = acc[i][j] * scale;
            if (s > t || amask[b * TT + s] == 0) v = -1e30f;
            C[(long)t * TT + s] = v;
        }
    }
}

// ---------------------------------------------------------------------------
// Row softmax over 1024 columns; one block (256 threads, 4 cols each) per row.
// ---------------------------------------------------------------------------
__global__ void softmax_k(float* __restrict__ scores)
{
    __shared__ float red[256];
    long row = blockIdx.x;
    float* p = scores + row * TT;
    int tid = threadIdx.x;
    float4 v = *(float4*)(p + tid * 4);
    float m = fmaxf(fmaxf(v.x, v.y), fmaxf(v.z, v.w));
    red[tid] = m; __syncthreads();
    for (int s = 128; s > 0; s >>= 1) {
        if (tid < s) red[tid] = fmaxf(red[tid], red[tid + s]);
        __syncthreads();
    }
    m = red[0]; __syncthreads();
    v.x = expf(v.x - m); v.y = expf(v.y - m);
    v.z = expf(v.z - m); v.w = expf(v.w - m);
    red[tid] = v.x + v.y + v.z + v.w; __syncthreads();
    for (int s = 128; s > 0; s >>= 1) {
        if (tid < s) red[tid] += red[tid + s];
        __syncthreads();
    }
    float inv = 1.0f / red[0];
    v.x *= inv; v.y *= inv; v.z *= inv; v.w *= inv;
    *(float4*)(p + tid * 4) = v;
}

// ---------------------------------------------------------------------------
// RMSNorm over first n columns of each row (row stride ld), in place.
// ---------------------------------------------------------------------------
__global__ void rmsnorm_k(float* __restrict__ x, const float* __restrict__ w,
                          int n, int ld)
{
    __shared__ float red[256];
    long row = blockIdx.x;
    float* p = x + row * ld;
    int tid = threadIdx.x;
    float ss = 0.f;
    for (int c = tid; c < n; c += 256) { float v = p[c]; ss += v * v; }
    red[tid] = ss; __syncthreads();
    for (int s = 128; s > 0; s >>= 1) {
        if (tid < s) red[tid] += red[tid + s];
        __syncthreads();
    }
    float r = rsqrtf(red[0] / (float)n + 1e-6f);
    for (int c = tid; c < n; c += 256) p[c] = p[c] * r * w[c];
}

// ---------------------------------------------------------------------------
// RoPE on q pe columns: per (token, head), cols [h*192+128, h*192+192).
// half-split: x1 = [0,32), x2 = [32,64).
// ---------------------------------------------------------------------------
__global__ void rope_q_k(float* __restrict__ q, const int* __restrict__ pos)
{
    int gid = blockIdx.x * 256 + threadIdx.x;   // B*T*H*32 = 2097152 threads
    int i = gid & 31;
    int row = gid >> 5;          // bt*32 + h
    int h = row & 31, bt = row >> 5;
    float p = (float)pos[bt];
    float invf = powf(10000.f, -(float)i / 32.f);
    float sn, cs;
    sincosf(p * invf, &sn, &cs);
    float* base = q + (long)bt * 6144 + h * 192 + 128;
    float x1 = base[i], x2 = base[32 + i];
    base[i]      = x1 * cs - x2 * sn;
    base[32 + i] = x1 * sn + x2 * cs;
}

// RoPE on shared key pe: kvout cols [512, 576) per token.
__global__ void rope_kpe_k(float* __restrict__ kvout, const int* __restrict__ pos)
{
    int gid = blockIdx.x * 256 + threadIdx.x;   // B*T*32 = 65536 threads
    int i = gid & 31;
    int bt = gid >> 5;
    float p = (float)pos[bt];
    float invf = powf(10000.f, -(float)i / 32.f);
    float sn, cs;
    sincosf(p * invf, &sn, &cs);
    float* base = kvout + (long)bt * 576 + 512;
    float x1 = base[i], x2 = base[32 + i];
    base[i]      = x1 * cs - x2 * sn;
    base[32 + i] = x1 * sn + x2 * cs;
}

// ---------------------------------------------------------------------------
extern "C" void kernel_launch(void* const* d_in, const int* in_sizes, int n_in,
                              void* d_out, int out_size)
{
    const float* x        = (const float*)d_in[0];
    const float* wq_a     = (const float*)d_in[1];
    const float* q_norm_w = (const float*)d_in[2];
    const float* wq_b     = (const float*)d_in[3];
    const float* wkv_a    = (const float*)d_in[4];
    const float* kv_norm_w= (const float*)d_in[5];
    const float* wkv_b    = (const float*)d_in[6];
    const float* wo       = (const float*)d_in[7];
    const int*   amask    = (const int*)d_in[8];
    const int*   pos      = (const int*)d_in[9];
    float*       out      = (float*)d_out;

    float *qlow, *qq, *kvout, *kvexp, *scores, *attn;
    cudaGetSymbolAddress((void**)&qlow,   g_qlow);
    cudaGetSymbolAddress((void**)&qq,     g_q);
    cudaGetSymbolAddress((void**)&kvout,  g_kvout);
    cudaGetSymbolAddress((void**)&kvexp,  g_kvexp);
    cudaGetSymbolAddress((void**)&scores, g_scores);
    cudaGetSymbolAddress((void**)&attn,   g_attn);

    dim3 blk(256);

    // 1. qlow = x @ wq_a          [2048,1536]
    gemm_nn_k<<<dim3(12, 16, 1), blk>>>(x, wq_a, qlow,
        2048, 1536, 4096, 4096, 1536, 1536, 0, 0, 0, 0, 0, 0, 1, 0);
    // 2. rmsnorm(qlow)
    rmsnorm_k<<<2048, 256>>>(qlow, q_norm_w, 1536, 1536);
    // 3. q = qlow @ wq_b          [2048,6144]
    gemm_nn_k<<<dim3(48, 16, 1), blk>>>(qlow, wq_b, qq,
        2048, 6144, 1536, 1536, 6144, 6144, 0, 0, 0, 0, 0, 0, 1, 0);
    // 4. kvout = x @ wkv_a        [2048,576]
    gemm_nn_k<<<dim3(5, 16, 1), blk>>>(x, wkv_a, kvout,
        2048, 576, 4096, 4096, 576, 576, 0, 0, 0, 0, 0, 0, 1, 0);
    // 5. rmsnorm(kvout[:, :512])
    rmsnorm_k<<<2048, 256>>>(kvout, kv_norm_w, 512, 576);
    // 6. rope
    rope_q_k<<<8192, 256>>>(qq, pos);
    rope_kpe_k<<<256, 256>>>(kvout, pos);
    // 7. kvexp = kvout[:, :512] @ wkv_b   [2048,8192]
    gemm_nn_k<<<dim3(64, 16, 1), blk>>>(kvout, wkv_b, kvexp,
        2048, 8192, 512, 576, 8192, 8192, 0, 0, 0, 0, 0, 0, 1, 0);
    // 8. scores
    scores_k<<<dim3(8, 8, 64), blk>>>(qq, kvexp, kvout, amask, scores);
    // 9. softmax rows
    softmax_k<<<65536, 256>>>(scores);
    // 10. attn_out = scores @ V (batched over b,h; causal K trim)
    gemm_nn_k<<<dim3(1, 8, 64), blk>>>(scores, kvexp + 128, attn,
        1024, 128, 1024, 1024, 8192, 4096,
        (long)32 * 1024 * 1024, (long)1024 * 1024,
        (long)1024 * 8192, 256,
        (long)1024 * 4096, 128,
        32, 1);
    // 11. out = attn_out @ wo     [2048,4096]
    gemm_nn_k<<<dim3(32, 16, 1), blk>>>(attn, wo, out,
        2048, 4096, 4096, 4096, 4096, 4096, 0, 0, 0, 0, 0, 0, 1, 0);
}

// round 4
// speedup vs baseline: 2.6077x; 2.6077x over previous
#include <cuda_runtime.h>
#include <cuda_bf16.h>
#include <math.h>
#include <stdint.h>

typedef __nv_bfloat16 bf16;
#define TT 1024
#define SCALE_QK 0.07216878364870323f

// ------------------------- device scratch (no cudaMalloc) -------------------
__device__ float g_qlow [2048*1536];
__device__ float g_q    [2048*6144];
__device__ float g_kvout[2048*576];
__device__ float g_kvexp[2048*8192];
__device__ float g_attn [2048*4096];
__device__ float g_scores[64ll*1024*1024];

__device__ bf16 g_xh[2048*4096],  g_xl[2048*4096];
__device__ bf16 g_qlh[2048*1536], g_qll[2048*1536];
__device__ bf16 g_qh[2048*6144],  g_ql[2048*6144];
__device__ bf16 g_kvh[2048*512],  g_kvl[2048*512];
__device__ bf16 g_kh[64ll*1024*192], g_kl[64ll*1024*192];
__device__ bf16 g_vth[64ll*128*1024], g_vtl[64ll*128*1024];
__device__ bf16 g_ph[64ll*1024*1024], g_pl[64ll*1024*1024];
__device__ bf16 g_ath[2048*4096], g_atl[2048*4096];
__device__ bf16 g_wqah[1536*4096], g_wqal[1536*4096];
__device__ bf16 g_wqbh[6144*1536], g_wqbl[6144*1536];
__device__ bf16 g_wkvah[576*4096], g_wkval[576*4096];
__device__ bf16 g_wkvbh[8192*512], g_wkvbl[8192*512];
__device__ bf16 g_woh[4096*4096],  g_wol[4096*4096];

// ------------------------------ PTX helpers (sm_80-safe) --------------------
__device__ __forceinline__ uint32_t smem_u32(const void* p) {
    uint32_t a;
    asm("{ .reg .u64 t; cvta.to.shared.u64 t, %1; cvt.u32.u64 %0, t; }"
        : "=r"(a) : "l"(p));
    return a;
}

#define LDSM4(r, a) asm volatile( \
    "ldmatrix.sync.aligned.m8n8.x4.shared.b16 {%0,%1,%2,%3}, [%4];" \
    : "=r"((r)[0]), "=r"((r)[1]), "=r"((r)[2]), "=r"((r)[3]) : "r"(a))

#define MMA16816(d, a, b0, b1) asm volatile( \
    "mma.sync.aligned.m16n8k16.row.col.f32.bf16.bf16.f32 " \
    "{%0,%1,%2,%3},{%4,%5,%6,%7},{%8,%9},{%0,%1,%2,%3};" \
    : "+f"((d)[0]), "+f"((d)[1]), "+f"((d)[2]), "+f"((d)[3]) \
    : "r"((a)[0]), "r"((a)[1]), "r"((a)[2]), "r"((a)[3]), "r"(b0), "r"(b1))

// cp.async 16B with zero-fill when invalid
__device__ __forceinline__ void cpa16(uint32_t dst, const void* src, int valid) {
    int sz = valid ? 16 : 0;
    asm volatile("cp.async.cg.shared.global [%0], [%1], 16, %2;"
                 :: "r"(dst), "l"(src), "r"(sz));
}

// Load one 128x32 bf16 plane into swizzled smem. rows < nvalid are real.
__device__ __forceinline__ void load_plane(uint32_t sb, const bf16* __restrict__ G,
                                           int row0, int ld, int k0, int tid,
                                           int nvalid) {
#pragma unroll
    for (int i = 0; i < 2; i++) {
        int idx = i * 256 + tid;
        int r = idx >> 2, c = idx & 3;
        uint32_t dst = sb + r * 64 + ((c ^ ((r >> 1) & 3)) << 4);
        int ok = r < nvalid;
        const bf16* src = G + (size_t)(row0 + (ok ? r : 0)) * ld + k0 + c * 8;
        cpa16(dst, src, ok);
    }
}

// ---------------------------------------------------------------------------
// 3-pass split-bf16 HMMA GEMM: C[M,N] = (Ah+Al)[M,K] @ (Bh+Bl)[N,K]^T * scale
// (drops Al*Bl). CTA 128x128, k-chunk 32, warps 2x4 (64x32 tiles).
// flags bit0: causal K-trim; bit1: skip tiles with n0 > m0.
// ---------------------------------------------------------------------------
#define GEMM_SMEM 65536
__global__ void __launch_bounds__(256, 1) gemm3_k(
    const bf16* __restrict__ Ah_, const bf16* __restrict__ Al_,
    const bf16* __restrict__ Bh_, const bf16* __restrict__ Bl_,
    float* __restrict__ C_,
    int N, int K, int lda, int ldb, int ldc,
    long aOut, long aIn, long bOut, long bIn, long cOut, long cIn,
    int innerCnt, int flags, float scale)
{
    extern __shared__ char smem[];
    int m0 = blockIdx.y * 128, n0 = blockIdx.x * 128;
    if ((flags & 2) && n0 > m0) return;

    int z = blockIdx.z, outer = z / innerCnt, inner = z - outer * innerCnt;
    const bf16* Ah = Ah_ + outer * aOut + inner * aIn;
    const bf16* Al = Al_ + outer * aOut + inner * aIn;
    const bf16* Bh = Bh_ + outer * bOut + inner * bIn;
    const bf16* Bl = Bl_ + outer * bOut + inner * bIn;
    float*      C  = C_  + outer * cOut + inner * cIn;

    int tid = threadIdx.x, lane = tid & 31, wid = tid >> 5;
    int mw = (wid & 1) * 64, nw = (wid >> 1) * 32;
    uint32_t s0 = smem_u32(smem);
    int nvB = min(128, N - n0);

    int Keff = (flags & 1) ? min(K, m0 + 128) : K;
    int nch = Keff >> 5;

    // precomputed ldmatrix row offsets + swizzle keys
    uint32_t rowA[4]; int sA[4];
#pragma unroll
    for (int mt = 0; mt < 4; mt++) {
        int r = mw + mt * 16 + (lane & 15);
        rowA[mt] = r * 64; sA[mt] = (r >> 1) & 3;
    }
    uint32_t rowB[2]; int sB[2];
#pragma unroll
    for (int h2 = 0; h2 < 2; h2++) {
        int r = nw + h2 * 16 + (lane & 7) + ((lane >> 4) << 3);
        rowB[h2] = r * 64; sB[h2] = (r >> 1) & 3;
    }
    int aCk = (lane >> 4) & 1;        // A chunk select within k16
    int bCk = (lane >> 3) & 1;        // B chunk select within k16

    float acc[4][4][4];
#pragma unroll
    for (int i = 0; i < 4; i++)
#pragma unroll
        for (int j = 0; j < 4; j++)
#pragma unroll
            for (int r = 0; r < 4; r++) acc[i][j][r] = 0.f;

    // prologue
    {
        uint32_t sb = s0;
        load_plane(sb,         Ah, m0, lda, 0, tid, 128);
        load_plane(sb + 8192,  Al, m0, lda, 0, tid, 128);
        load_plane(sb + 16384, Bh, n0, ldb, 0, tid, nvB);
        load_plane(sb + 24576, Bl, n0, ldb, 0, tid, nvB);
        asm volatile("cp.async.commit_group;" ::: "memory");
    }

    for (int c = 0; c < nch; c++) {
        if (c + 1 < nch) {
            uint32_t sb = s0 + ((c + 1) & 1) * 32768;
            int k0 = (c + 1) * 32;
            load_plane(sb,         Ah, m0, lda, k0, tid, 128);
            load_plane(sb + 8192,  Al, m0, lda, k0, tid, 128);
            load_plane(sb + 16384, Bh, n0, ldb, k0, tid, nvB);
            load_plane(sb + 24576, Bl, n0, ldb, k0, tid, nvB);
            asm volatile("cp.async.commit_group;" ::: "memory");
            asm volatile("cp.async.wait_group 1;" ::: "memory");
        } else {
            asm volatile("cp.async.wait_group 0;" ::: "memory");
        }
        __syncthreads();

        uint32_t base = s0 + (c & 1) * 32768;
        uint32_t pAh = base, pAl = base + 8192;
        uint32_t pBh = base + 16384, pBl = base + 24576;
#pragma unroll
        for (int ks = 0; ks < 2; ks++) {
            uint32_t af[4][4], bhf[2][4], blf[2][4];
            int cA = ks * 2 + aCk, cB = ks * 2 + bCk;
#pragma unroll
            for (int mt = 0; mt < 4; mt++)
                LDSM4(af[mt], pAh + rowA[mt] + (uint32_t)((cA ^ sA[mt]) << 4));
#pragma unroll
            for (int h2 = 0; h2 < 2; h2++) {
                LDSM4(bhf[h2], pBh + rowB[h2] + (uint32_t)((cB ^ sB[h2]) << 4));
                LDSM4(blf[h2], pBl + rowB[h2] + (uint32_t)((cB ^ sB[h2]) << 4));
            }
            // Ah * Bh
#pragma unroll
            for (int mt = 0; mt < 4; mt++)
#pragma unroll
                for (int nt = 0; nt < 4; nt++)
                    MMA16816(acc[mt][nt], af[mt],
                             bhf[nt >> 1][(nt & 1) * 2], bhf[nt >> 1][(nt & 1) * 2 + 1]);
            // Ah * Bl
#pragma unroll
            for (int mt = 0; mt < 4; mt++)
#pragma unroll
                for (int nt = 0; nt < 4; nt++)
                    MMA16816(acc[mt][nt], af[mt],
                             blf[nt >> 1][(nt & 1) * 2], blf[nt >> 1][(nt & 1) * 2 + 1]);
            // Al * Bh (reuse A regs)
#pragma unroll
            for (int mt = 0; mt < 4; mt++)
                LDSM4(af[mt], pAl + rowA[mt] + (uint32_t)((cA ^ sA[mt]) << 4));
#pragma unroll
            for (int mt = 0; mt < 4; mt++)
#pragma unroll
                for (int nt = 0; nt < 4; nt++)
                    MMA16816(acc[mt][nt], af[mt],
                             bhf[nt >> 1][(nt & 1) * 2], bhf[nt >> 1][(nt & 1) * 2 + 1]);
        }
        __syncthreads();
    }

    // epilogue: fragment -> global fp32 (float2 stores)
#pragma unroll
    for (int mt = 0; mt < 4; mt++) {
        int r0 = m0 + mw + mt * 16 + (lane >> 2);
#pragma unroll
        for (int nt = 0; nt < 4; nt++) {
            int col = n0 + nw + nt * 8 + 2 * (lane & 3);
            if (col < N) {
                float2 v0 = make_float2(acc[mt][nt][0] * scale, acc[mt][nt][1] * scale);
                float2 v1 = make_float2(acc[mt][nt][2] * scale, acc[mt][nt][3] * scale);
                *(float2*)(C + (size_t)r0 * ldc + col) = v0;
                *(float2*)(C + (size_t)(r0 + 8) * ldc + col) = v1;
            }
        }
    }
}

// ------------------------- conversion / elementwise -------------------------
__device__ __forceinline__ void split1(float v, bf16* h, bf16* l, size_t i) {
    bf16 hi = __float2bfloat16(v);
    h[i] = hi;
    l[i] = __float2bfloat16(v - __bfloat162float(hi));
}

__global__ void split_k(const float* __restrict__ x, bf16* __restrict__ h,
                        bf16* __restrict__ l, long n) {
    long i = blockIdx.x * 256ll + threadIdx.x;
    if (i < n) split1(x[i], h, l, i);
}

// W[K][N] fp32 -> Th/Tl[N][K] bf16 (tiled transpose)
__global__ void wtsplit_k(const float* __restrict__ W, bf16* __restrict__ Th,
                          bf16* __restrict__ Tl, int K, int N) {
    __shared__ float t[32][33];
    int n0 = blockIdx.x * 32, k0 = blockIdx.y * 32;
    int tx = threadIdx.x, ty = threadIdx.y;
#pragma unroll
    for (int j = 0; j < 32; j += 8)
        t[ty + j][tx] = W[(size_t)(k0 + ty + j) * N + n0 + tx];
    __syncthreads();
#pragma unroll
    for (int j = 0; j < 32; j += 8)
        split1(t[tx][ty + j], Th, Tl, (size_t)(n0 + ty + j) * K + k0 + tx);
}

__global__ void rmsns_k(const float* __restrict__ x, const float* __restrict__ w,
                        bf16* __restrict__ h, bf16* __restrict__ l, int n, int lds) {
    __shared__ float red[256];
    long row = blockIdx.x;
    const float* p = x + row * lds;
    int tid = threadIdx.x;
    float ss = 0.f;
    for (int c = tid; c < n; c += 256) { float v = p[c]; ss += v * v; }
    red[tid] = ss; __syncthreads();
    for (int s = 128; s > 0; s >>= 1) {
        if (tid < s) red[tid] += red[tid + s];
        __syncthreads();
    }
    float r = rsqrtf(red[0] / (float)n + 1e-6f);
    for (int c = tid; c < n; c += 256)
        split1(p[c] * r * w[c], h, l, row * n + c);
}

__global__ void rope_q_k(float* __restrict__ q, const int* __restrict__ pos) {
    int gid = blockIdx.x * 256 + threadIdx.x;      // B*T*H*32
    int i = gid & 31, row = gid >> 5;
    int h = row & 31, bt = row >> 5;
    float p = (float)pos[bt];
    float invf = powf(10000.f, -(float)i / 32.f);
    float sn, cs; sincosf(p * invf, &sn, &cs);
    float* base = q + (size_t)bt * 6144 + h * 192 + 128;
    float x1 = base[i], x2 = base[32 + i];
    base[i]      = x1 * cs - x2 * sn;
    base[32 + i] = x1 * sn + x2 * cs;
}

__global__ void rope_kpe_k(float* __restrict__ kvout, const int* __restrict__ pos) {
    int gid = blockIdx.x * 256 + threadIdx.x;      // B*T*32
    int i = gid & 31, bt = gid >> 5;
    float p = (float)pos[bt];
    float invf = powf(10000.f, -(float)i / 32.f);
    float sn, cs; sincosf(p * invf, &sn, &cs);
    float* base = kvout + (size_t)bt * 576 + 512;
    float x1 = base[i], x2 = base[32 + i];
    base[i]      = x1 * cs - x2 * sn;
    base[32 + i] = x1 * sn + x2 * cs;
}

// K gather: [bh][s][192] from kvexp nope cols + roped shared pe
__global__ void kgather_k(const float* __restrict__ kvexp,
                          const float* __restrict__ kvout,
                          bf16* __restrict__ kh, bf16* __restrict__ kl) {
    long gid = blockIdx.x * 256ll + threadIdx.x;   // 64*1024*192
    int k = (int)(gid % 192);
    long r = gid / 192;
    int s = (int)(r & 1023), bh = (int)(r >> 10);
    int b = bh >> 5, h = bh & 31;
    float v = (k < 128)
        ? kvexp[((size_t)b * 1024 + s) * 8192 + h * 256 + k]
        : kvout[((size_t)b * 1024 + s) * 576 + 512 + (k - 128)];
    split1(v, kh, kl, gid);
}

// V transpose: [bh][d=128][s=1024]
__global__ void vtrans_k(const float* __restrict__ kvexp,
                         bf16* __restrict__ vh, bf16* __restrict__ vl) {
    long gid = blockIdx.x * 256ll + threadIdx.x;   // 64*128*1024
    int s = (int)(gid & 1023);
    long r = gid >> 10;
    int d = (int)(r & 127), bh = (int)(r >> 7);
    int b = bh >> 5, h = bh & 31;
    float v = kvexp[((size_t)b * 1024 + s) * 8192 + h * 256 + 128 + d];
    split1(v, vh, vl, gid);
}

// softmax over causal prefix -> P hi/lo planes (cols [0, send) defined)
__global__ void smax_k(const float* __restrict__ sc, const int* __restrict__ amask,
                       bf16* __restrict__ ph, bf16* __restrict__ pl) {
    __shared__ float red[128];
    int rb = blockIdx.x;
    int t = rb & 1023, bh = rb >> 10, b = bh >> 5;
    const float* p = sc + (size_t)bh * 1048576 + (size_t)t * 1024;
    int send = ((t >> 7) + 1) << 7;
    int tid = threadIdx.x, cnt = send >> 7;
    float vals[8], m = -1e30f;
    for (int i = 0; i < cnt; i++) {
        int s = tid + i * 128;
        float v = (s <= t && amask[b * 1024 + s] != 0) ? p[s] : -1e30f;
        vals[i] = v; m = fmaxf(m, v);
    }
    red[tid] = m; __syncthreads();
    for (int st = 64; st > 0; st >>= 1) {
        if (tid < st) red[tid] = fmaxf(red[tid], red[tid + st]);
        __syncthreads();
    }
    m = red[0]; __syncthreads();
    float sum = 0.f;
    for (int i = 0; i < cnt; i++) { float e = expf(vals[i] - m); vals[i] = e; sum += e; }
    red[tid] = sum; __syncthreads();
    for (int st = 64; st > 0; st >>= 1) {
        if (tid < st) red[tid] += red[tid + st];
        __syncthreads();
    }
    float inv = 1.f / red[0];
    bf16* oh = ph + (size_t)bh * 1048576 + (size_t)t * 1024;
    bf16* ol = pl + (size_t)bh * 1048576 + (size_t)t * 1024;
    for (int i = 0; i < cnt; i++) {
        int s = tid + i * 128;
        float v = vals[i] * inv;
        bf16 hi = __float2bfloat16(v);
        oh[s] = hi;
        ol[s] = __float2bfloat16(v - __bfloat162float(hi));
    }
}

// ---------------------------------------------------------------------------
extern "C" void kernel_launch(void* const* d_in, const int* in_sizes, int n_in,
                              void* d_out, int out_size)
{
    const float* x        = (const float*)d_in[0];
    const float* wq_a     = (const float*)d_in[1];
    const float* q_norm_w = (const float*)d_in[2];
    const float* wq_b     = (const float*)d_in[3];
    const float* wkv_a    = (const float*)d_in[4];
    const float* kv_norm_w= (const float*)d_in[5];
    const float* wkv_b    = (const float*)d_in[6];
    const float* wo       = (const float*)d_in[7];
    const int*   amask    = (const int*)d_in[8];
    const int*   pos      = (const int*)d_in[9];
    float*       out      = (float*)d_out;

    cudaFuncSetAttribute(gemm3_k, cudaFuncAttributeMaxDynamicSharedMemorySize,
                         GEMM_SMEM);

    float *qlow, *qf, *kvout, *kvexp, *attnf, *scores;
    bf16 *xh,*xl,*qlh,*qll,*qh,*ql,*kvh,*kvl,*kh,*kl,*vth,*vtl,*ph,*pl,*ath,*atl;
    bf16 *wqah,*wqal,*wqbh,*wqbl,*wkvah,*wkval,*wkvbh,*wkvbl,*woh,*wol;
    cudaGetSymbolAddress((void**)&qlow, g_qlow);
    cudaGetSymbolAddress((void**)&qf,   g_q);
    cudaGetSymbolAddress((void**)&kvout,g_kvout);
    cudaGetSymbolAddress((void**)&kvexp,g_kvexp);
    cudaGetSymbolAddress((void**)&attnf,g_attn);
    cudaGetSymbolAddress((void**)&scores,g_scores);
    cudaGetSymbolAddress((void**)&xh, g_xh);   cudaGetSymbolAddress((void**)&xl, g_xl);
    cudaGetSymbolAddress((void**)&qlh,g_qlh);  cudaGetSymbolAddress((void**)&qll,g_qll);
    cudaGetSymbolAddress((void**)&qh, g_qh);   cudaGetSymbolAddress((void**)&ql, g_ql);
    cudaGetSymbolAddress((void**)&kvh,g_kvh);  cudaGetSymbolAddress((void**)&kvl,g_kvl);
    cudaGetSymbolAddress((void**)&kh, g_kh);   cudaGetSymbolAddress((void**)&kl, g_kl);
    cudaGetSymbolAddress((void**)&vth,g_vth);  cudaGetSymbolAddress((void**)&vtl,g_vtl);
    cudaGetSymbolAddress((void**)&ph, g_ph);   cudaGetSymbolAddress((void**)&pl, g_pl);
    cudaGetSymbolAddress((void**)&ath,g_ath);  cudaGetSymbolAddress((void**)&atl,g_atl);
    cudaGetSymbolAddress((void**)&wqah,g_wqah); cudaGetSymbolAddress((void**)&wqal,g_wqal);
    cudaGetSymbolAddress((void**)&wqbh,g_wqbh); cudaGetSymbolAddress((void**)&wqbl,g_wqbl);
    cudaGetSymbolAddress((void**)&wkvah,g_wkvah); cudaGetSymbolAddress((void**)&wkval,g_wkval);
    cudaGetSymbolAddress((void**)&wkvbh,g_wkvbh); cudaGetSymbolAddress((void**)&wkvbl,g_wkvbl);
    cudaGetSymbolAddress((void**)&woh,g_woh);   cudaGetSymbolAddress((void**)&wol,g_wol);

    dim3 tb(32, 8);
    // weight transpose+split
    wtsplit_k<<<dim3(48, 128), tb>>>(wq_a, wqah, wqal, 4096, 1536);
    wtsplit_k<<<dim3(192, 48), tb>>>(wq_b, wqbh, wqbl, 1536, 6144);
    wtsplit_k<<<dim3(18, 128), tb>>>(wkv_a, wkvah, wkval, 4096, 576);
    wtsplit_k<<<dim3(256, 16), tb>>>(wkv_b, wkvbh, wkvbl, 512, 8192);
    wtsplit_k<<<dim3(128, 128), tb>>>(wo, woh, wol, 4096, 4096);
    split_k<<<32768, 256>>>(x, xh, xl, 2048ll * 4096);

    // 1. qlow = x @ wq_a
    gemm3_k<<<dim3(12, 16, 1), 256, GEMM_SMEM>>>(xh, xl, wqah, wqal, qlow,
        1536, 4096, 4096, 4096, 1536, 0,0,0,0,0,0, 1, 0, 1.f);
    // 2. rmsnorm -> hi/lo
    rmsns_k<<<2048, 256>>>(qlow, q_norm_w, qlh, qll, 1536, 1536);
    // 3. q = qlow @ wq_b
    gemm3_k<<<dim3(48, 16, 1), 256, GEMM_SMEM>>>(qlh, qll, wqbh, wqbl, qf,
        6144, 1536, 1536, 1536, 6144, 0,0,0,0,0,0, 1, 0, 1.f);
    // 4. kvout = x @ wkv_a
    gemm3_k<<<dim3(5, 16, 1), 256, GEMM_SMEM>>>(xh, xl, wkvah, wkval, kvout,
        576, 4096, 4096, 4096, 576, 0,0,0,0,0,0, 1, 0, 1.f);
    // 5. rmsnorm kv -> hi/lo; rope
    rmsns_k<<<2048, 256>>>(kvout, kv_norm_w, kvh, kvl, 512, 576);
    rope_q_k<<<8192, 256>>>(qf, pos);
    rope_kpe_k<<<256, 256>>>(kvout, pos);
    split_k<<<49152, 256>>>(qf, qh, ql, 2048ll * 6144);
    // 7. kvexp = kv @ wkv_b
    gemm3_k<<<dim3(64, 16, 1), 256, GEMM_SMEM>>>(kvh, kvl, wkvbh, wkvbl, kvexp,
        8192, 512, 512, 512, 8192, 0,0,0,0,0,0, 1, 0, 1.f);
    // 8. per-head K gather + V transpose
    kgather_k<<<49152, 256>>>(kvexp, kvout, kh, kl);
    vtrans_k<<<32768, 256>>>(kvexp, vth, vtl);
    // 9. scores = scale * Q @ K^T (lower-triangular tiles only)
    gemm3_k<<<dim3(8, 8, 64), 256, GEMM_SMEM>>>(qh, ql, kh, kl, scores,
        1024, 192, 6144, 192, 1024,
        (long)1024 * 6144, 192, 32ll * 1024 * 192, (long)1024 * 192,
        32ll * 1024 * 1024, (long)1024 * 1024, 32, 2, SCALE_QK);
    // 10. softmax -> P hi/lo planes
    smax_k<<<65536, 128>>>(scores, amask, ph, pl);
    // 11. attn = P @ V (causal K-trim)
    gemm3_k<<<dim3(1, 8, 64), 256, GEMM_SMEM>>>(ph, pl, vth, vtl, attnf,
        128, 1024, 1024, 1024, 4096,
        32ll * 1024 * 1024, (long)1024 * 1024, 32ll * 128 * 1024, (long)128 * 1024,
        (long)1024 * 4096, 128, 32, 1, 1.f);
    // 12. split attn, final projection
    split_k<<<32768, 256>>>(attnf, ath, atl, 2048ll * 4096);
    gemm3_k<<<dim3(32, 16, 1), 256, GEMM_SMEM>>>(ath, atl, woh, wol, out,
        4096, 4096, 4096, 4096, 4096, 0,0,0,0,0,0, 1, 0, 1.f);
}